// round 10
// baseline (speedup 1.0000x reference)
#include <cuda_runtime.h>
#include <math.h>
#include <cstdint>

// ---------------- problem constants ----------------
#define BN_ 16384
#define D_IN 1024
#define H1 512
#define H2 256
#define H3 128
#define FH 64
#define NDOM 4
#define EMB 16
#define BMROWS 128
#define BP 16896            // 132 tiles of 128 (>= 16384 + max padding 508)
#define NCB 64              // count blocks

// ---------------- scratch (device globals) ----------------
__device__ float g_norm[(size_t)BP * D_IN];
__device__ float g_h1c[(size_t)BP * H1];
__device__ float g_h1d[(size_t)BP * H1];
__device__ float g_h2c[(size_t)BP * H2];
__device__ float g_h2d[(size_t)BP * H2];
__device__ float g_h3c[(size_t)BP * H3];
__device__ float g_h3d[(size_t)BP * H3];
__device__ int   g_perm[BP];
__device__ int   g_bcnt[NCB][NDOM];
__device__ int   g_cnt[NDOM];
__device__ int   g_off[NDOM];
__device__ float g_aux[NDOM];

typedef unsigned long long u64;

// ---------------- f32x2 helpers ----------------
__device__ __forceinline__ u64 pack2(float x) {
    u64 r;
    asm("mov.b64 %0, {%1, %1};" : "=l"(r) : "r"(__float_as_uint(x)));
    return r;
}
__device__ __forceinline__ void fma2(u64& d, u64 a, u64 b) {
    asm("fma.rn.f32x2 %0, %1, %2, %0;" : "+l"(d) : "l"(a), "l"(b));
}
__device__ __forceinline__ float2 unpack2(u64 v) {
    uint32_t lo, hi;
    asm("mov.b64 {%0, %1}, %2;" : "=r"(lo), "=r"(hi) : "l"(v));
    float2 f;
    f.x = __uint_as_float(lo);
    f.y = __uint_as_float(hi);
    return f;
}

// pad region helpers
__device__ __forceinline__ int pad4(int c) { return (c + BMROWS - 1) & ~(BMROWS - 1); }

__device__ __forceinline__ int dom_of(int p) {
    int d = 0;
    #pragma unroll
    for (int k = 1; k < NDOM; k++) d += (p >= g_off[k]);
    return d;
}

// ---------------- sort: count (per-block partials) ----------------
__global__ __launch_bounds__(256) void count_kernel(const int* __restrict__ dids) {
    __shared__ int sc[NDOM];
    int tid = threadIdx.x;
    if (tid < NDOM) sc[tid] = 0;
    __syncthreads();
    int i = blockIdx.x * 256 + tid;
    atomicAdd(&sc[dids[i]], 1);
    __syncthreads();
    if (tid < NDOM) g_bcnt[blockIdx.x][tid] = sc[tid];
}

// ---------------- sort: scatter with inline prefix (publishes off/cnt) ----------------
__global__ __launch_bounds__(256) void scatter_kernel(const int* __restrict__ dids) {
    __shared__ int pre[NDOM];
    __shared__ int loc[NDOM];
    __shared__ int stot[NDOM], sbase[NDOM];
    int tid = threadIdx.x;
    if (tid < NDOM) {
        int d = tid, base = 0, tot = 0;
        #pragma unroll 8
        for (int b = 0; b < NCB; b++) {
            int c = g_bcnt[b][d];
            if (b < (int)blockIdx.x) base += c;
            tot += c;
        }
        stot[d] = tot; sbase[d] = base;
        loc[d] = 0;
    }
    __syncthreads();
    if (tid == 0) {
        int off = 0;
        #pragma unroll
        for (int d = 0; d < NDOM; d++) {
            pre[d] = off + sbase[d];
            if (blockIdx.x == 0) { g_off[d] = off; g_cnt[d] = stot[d]; }
            off += pad4(stot[d]);
        }
    }
    __syncthreads();
    int i = blockIdx.x * 256 + tid;
    int d = dids[i];
    int rank = atomicAdd(&loc[d], 1);
    g_perm[pre[d] + rank] = i;
}

// aux net (domain-only) -> 4 scalars
__global__ void aux_kernel(const float* __restrict__ dom_emb,
                           const float* __restrict__ aW1, const float* __restrict__ ab1,
                           const float* __restrict__ aW2, const float* __restrict__ ab2) {
    int w = threadIdx.x >> 5;
    int j = threadIdx.x & 31;
    float s = ab1[j];
    #pragma unroll
    for (int i = 0; i < EMB; i++) s += dom_emb[w * EMB + i] * aW1[i * 32 + j];
    float v = fmaxf(s, 0.f) * aW2[j];
    #pragma unroll
    for (int o = 16; o; o >>= 1) v += __shfl_xor_sync(0xFFFFFFFFu, v, o);
    if (j == 0) g_aux[w] = v + ab2[0];
}

// ---------------- layernorm + domain affine, permuted order ----------------
__global__ __launch_bounds__(256) void ln_kernel(const float* __restrict__ x,
                                                 const int* __restrict__ dids,
                                                 const float* __restrict__ pnw,
                                                 const float* __restrict__ pnb) {
    int p = blockIdx.x;
    int tid = threadIdx.x;
    float* out = g_norm + (size_t)p * D_IN;
    int d0 = dom_of(p);
    bool pad = (p - g_off[d0]) >= g_cnt[d0];
    if (pad) {
        float4 z = {0.f, 0.f, 0.f, 0.f};
        *(float4*)&out[tid * 4] = z;
        return;
    }
    int r = g_perm[p];
    const float* xr = x + (size_t)r * D_IN;
    float4 v = *(const float4*)&xr[tid * 4];
    float s = v.x + v.y + v.z + v.w;
    float q = v.x * v.x + v.y * v.y + v.z * v.z + v.w * v.w;
    #pragma unroll
    for (int o = 16; o; o >>= 1) {
        s += __shfl_xor_sync(0xFFFFFFFFu, s, o);
        q += __shfl_xor_sync(0xFFFFFFFFu, q, o);
    }
    __shared__ float ss[8], sq[8];
    __shared__ float smean, sinv;
    if ((tid & 31) == 0) { ss[tid >> 5] = s; sq[tid >> 5] = q; }
    __syncthreads();
    if (tid < 32) {
        s = (tid < 8) ? ss[tid] : 0.f;
        q = (tid < 8) ? sq[tid] : 0.f;
        #pragma unroll
        for (int o = 4; o; o >>= 1) {
            s += __shfl_xor_sync(0xFFFFFFFFu, s, o);
            q += __shfl_xor_sync(0xFFFFFFFFu, q, o);
        }
        if (tid == 0) {
            float mean = s * (1.f / D_IN);
            float var = q * (1.f / D_IN) - mean * mean;
            smean = mean;
            sinv = rsqrtf(var + 1e-5f);
        }
    }
    __syncthreads();
    int d = dids[r];
    float4 w = *(const float4*)&pnw[(size_t)d * D_IN + tid * 4];
    float4 b = *(const float4*)&pnb[(size_t)d * D_IN + tid * 4];
    float m = smean, inv = sinv;
    float4 o;
    o.x = (v.x - m) * inv * w.x + b.x;
    o.y = (v.y - m) * inv * w.y + b.y;
    o.z = (v.z - m) * inv * w.z + b.z;
    o.w = (v.w - m) * inv * w.w + b.w;
    *(float4*)&out[tid * 4] = o;
}

// ---------------- tiled GEMM v5: B streamed from L2 via registers ----------------
// A: LDG->regs pre-barrier, STS-after-compute into 2-stage As (1 barrier/tile, race-free).
// B: NO smem. Per k-row, each thread LDG.128s its 8 columns straight from L2 into a
// 3-deep rotating register ring, prefetched 2 rows ahead (period ~512cyc >> L2 262cyc).
template <int K, int N, bool RELU, int LAYER>
__global__ __launch_bounds__(256, 2) void gemm_kernel(const float* __restrict__ Wc,
                                                      const float* __restrict__ Wd,
                                                      const float* __restrict__ bc,
                                                      const float* __restrict__ bd) {
    constexpr int BM = 128, BK = 16;
    __shared__ float As[2][BK][BM];    // 2 x 8KB

    const int tid = threadIdx.x;
    const int tx = tid & 15, ty = tid >> 4;
    const int by = blockIdx.y, bx = blockIdx.x;
    const int z = blockIdx.z;
    const int m0 = by * BM;
    const int n0 = bx * 128;

    const float* A; float* C;
    if constexpr (LAYER == 1) { A = g_norm;               C = z ? g_h1d : g_h1c; }
    if constexpr (LAYER == 2) { A = z ? g_h1d : g_h1c;    C = z ? g_h2d : g_h2c; }
    if constexpr (LAYER == 3) { A = z ? g_h2d : g_h2c;    C = z ? g_h3d : g_h3c; }

    const float* W; const float* bias;
    if (z == 0) { W = Wc; bias = bc; }
    else {
        int dom = dom_of(m0);
        W = Wd + (size_t)dom * K * N;
        bias = bd + (size_t)dom * N;
    }

    // B stream base for this thread: columns n0+tx*4 and +64
    const float* Bp0 = W + n0 + tx * 4;
    const float* Bp1 = Bp0 + 64;

    // A loader coords
    const int ar0 = tid >> 2, ar1 = ar0 + 64;       // via +256 trick: (tid+256)>>2 = ar0+64
    const int ac0 = (tid & 3) * 4;

    u64 acc[8][4];
    #pragma unroll
    for (int i = 0; i < 8; i++)
        #pragma unroll
        for (int j = 0; j < 4; j++) acc[i][j] = 0ull;

    constexpr int NT = K / BK;

    // B register ring: 3 slots x 4 u64
    u64 bb[3][4];
    auto loadB = [&](int r, u64* dst) {   // global k-row r
        float4 v0 = *(const float4*)(Bp0 + (size_t)r * N);
        float4 v1 = *(const float4*)(Bp1 + (size_t)r * N);
        dst[0] = ((const u64*)&v0)[0];
        dst[1] = ((const u64*)&v0)[1];
        dst[2] = ((const u64*)&v1)[0];
        dst[3] = ((const u64*)&v1)[1];
    };

    auto ldgA = [&](int t, float4* av) {
        const float* src = A + (size_t)m0 * K + t * BK;
        av[0] = *(const float4*)&src[(size_t)ar0 * K + ac0];
        av[1] = *(const float4*)&src[(size_t)ar1 * K + ac0];
    };
    auto stsA = [&](int st, const float4* av) {
        As[st][ac0 + 0][ar0] = av[0].x;
        As[st][ac0 + 1][ar0] = av[0].y;
        As[st][ac0 + 2][ar0] = av[0].z;
        As[st][ac0 + 3][ar0] = av[0].w;
        As[st][ac0 + 0][ar1] = av[1].x;
        As[st][ac0 + 1][ar1] = av[1].y;
        As[st][ac0 + 2][ar1] = av[1].z;
        As[st][ac0 + 3][ar1] = av[1].w;
    };

    // prologue: A(0) -> As[0]; B rows 0,1 -> ring
    float4 av[2];
    ldgA(0, av);
    stsA(0, av);
    loadB(0, bb[0]);
    loadB(1, bb[1]);

    for (int t = 0; t < NT; t++) {
        const int s = t & 1;
        if (t + 1 < NT) ldgA(t + 1, av);          // private regs, race-free
        __syncthreads();                           // As[s] ready for all

        #pragma unroll
        for (int kk = 0; kk < BK; kk++) {
            const int r = t * BK + kk;
            if (r + 2 < K) loadB(r + 2, bb[(r + 2) % 3]);   // dist-2 prefetch
            float a[8];
            *(float4*)&a[0] = *(const float4*)&As[s][kk][ty * 4];
            *(float4*)&a[4] = *(const float4*)&As[s][kk][ty * 4 + 64];
            const u64* b = bb[r % 3];
            u64 b0 = b[0], b1 = b[1], b2 = b[2], b3 = b[3];
            #pragma unroll
            for (int i = 0; i < 8; i++) {
                u64 ai = pack2(a[i]);
                fma2(acc[i][0], ai, b0);
                fma2(acc[i][1], ai, b1);
                fma2(acc[i][2], ai, b2);
                fma2(acc[i][3], ai, b3);
            }
        }

        if (t + 1 < NT) stsA(s ^ 1, av);          // after compute: all warps passed barrier(t)
    }

    float bj[8];
    #pragma unroll
    for (int j = 0; j < 8; j++) {
        int cn = tx * 4 + (j & 3) + ((j >> 2) * 64);
        bj[j] = bias[n0 + cn];
    }
    #pragma unroll
    for (int i = 0; i < 8; i++) {
        int m = m0 + ty * 4 + (i & 3) + ((i >> 2) * 64);
        float2 c0 = unpack2(acc[i][0]);
        float2 c1 = unpack2(acc[i][1]);
        float2 c2 = unpack2(acc[i][2]);
        float2 c3 = unpack2(acc[i][3]);
        float4 o0, o1;
        o0.x = c0.x + bj[0]; o0.y = c0.y + bj[1];
        o0.z = c1.x + bj[2]; o0.w = c1.y + bj[3];
        o1.x = c2.x + bj[4]; o1.y = c2.y + bj[5];
        o1.z = c3.x + bj[6]; o1.w = c3.y + bj[7];
        if (RELU) {
            o0.x = fmaxf(o0.x, 0.f); o0.y = fmaxf(o0.y, 0.f);
            o0.z = fmaxf(o0.z, 0.f); o0.w = fmaxf(o0.w, 0.f);
            o1.x = fmaxf(o1.x, 0.f); o1.y = fmaxf(o1.y, 0.f);
            o1.z = fmaxf(o1.z, 0.f); o1.w = fmaxf(o1.w, 0.f);
        }
        *(float4*)&C[(size_t)m * N + n0 + tx * 4]      = o0;
        *(float4*)&C[(size_t)m * N + n0 + tx * 4 + 64] = o1;
    }
}

// ---------------- fuse + final MLP + aux + sigmoid (one warp per row) ----------------
__global__ __launch_bounds__(256) void final_kernel(const float* __restrict__ fW1,
                                                    const float* __restrict__ fb1,
                                                    const float* __restrict__ fW2,
                                                    const float* __restrict__ fb2,
                                                    float* __restrict__ out) {
    __shared__ float sW1[H3 * FH];
    __shared__ float sb1[FH], sW2[FH];
    __shared__ float sf[8][H3];

    int tid = threadIdx.x;
    for (int i = tid; i < H3 * FH; i += 256) sW1[i] = fW1[i];
    if (tid < FH) { sb1[tid] = fb1[tid]; sW2[tid] = fW2[tid]; }
    __syncthreads();

    int w = tid >> 5, lane = tid & 31;
    int p = blockIdx.x * 8 + w;
    int d0 = dom_of(p);
    bool pad = (p - g_off[d0]) >= g_cnt[d0];

    #pragma unroll
    for (int q = 0; q < 4; q++) {
        int i = q * 32 + lane;
        float c = g_h3c[(size_t)p * H3 + i];
        float d = g_h3d[(size_t)p * H3 + i];
        sf[w][i] = c * tanhf(d);
    }
    __syncwarp();

    float acc = 0.f;
    #pragma unroll
    for (int jj = 0; jj < 2; jj++) {
        int j = jj * 32 + lane;
        float h = sb1[j];
        #pragma unroll 8
        for (int i = 0; i < H3; i++) h += sf[w][i] * sW1[i * FH + j];
        acc += fmaxf(h, 0.f) * sW2[j];
    }
    #pragma unroll
    for (int o = 16; o; o >>= 1) acc += __shfl_xor_sync(0xFFFFFFFFu, acc, o);

    if (lane == 0 && !pad) {
        int r = g_perm[p];
        float v = acc + fb2[0] + g_aux[d0];
        out[r] = 1.f / (1.f + expf(-v));
    }
}

// ---------------- launch ----------------
extern "C" void kernel_launch(void* const* d_in, const int* in_sizes, int n_in,
                              void* d_out, int out_size) {
    const float* x      = (const float*)d_in[0];
    const int*   dids   = (const int*)  d_in[1];
    const float* pnw    = (const float*)d_in[2];
    const float* pnb    = (const float*)d_in[3];
    const float* cW1    = (const float*)d_in[4];
    const float* cb1    = (const float*)d_in[5];
    const float* cW2    = (const float*)d_in[6];
    const float* cb2    = (const float*)d_in[7];
    const float* cW3    = (const float*)d_in[8];
    const float* cb3    = (const float*)d_in[9];
    const float* dW1    = (const float*)d_in[10];
    const float* db1    = (const float*)d_in[11];
    const float* dW2    = (const float*)d_in[12];
    const float* db2    = (const float*)d_in[13];
    const float* dW3    = (const float*)d_in[14];
    const float* db3    = (const float*)d_in[15];
    const float* fW1    = (const float*)d_in[16];
    const float* fb1    = (const float*)d_in[17];
    const float* fW2    = (const float*)d_in[18];
    const float* fb2    = (const float*)d_in[19];
    const float* dom_emb= (const float*)d_in[20];
    const float* aW1    = (const float*)d_in[21];
    const float* ab1    = (const float*)d_in[22];
    const float* aW2    = (const float*)d_in[23];
    const float* ab2    = (const float*)d_in[24];
    float* out = (float*)d_out;

    count_kernel<<<NCB, 256>>>(dids);                 // 0
    scatter_kernel<<<NCB, 256>>>(dids);               // 1
    ln_kernel<<<BP, 256>>>(x, dids, pnw, pnb);        // 2

    gemm_kernel<D_IN, H1, true,  1>                   // 3
        <<<dim3(H1 / 128, BP / 128, 2), 256>>>(cW1, dW1, cb1, db1);
    gemm_kernel<H1,   H2, true,  2>                   // 4
        <<<dim3(H2 / 128, BP / 128, 2), 256>>>(cW2, dW2, cb2, db2);
    gemm_kernel<H2,   H3, false, 3>                   // 5
        <<<dim3(H3 / 128, BP / 128, 2), 256>>>(cW3, dW3, cb3, db3);

    aux_kernel<<<1, 128>>>(dom_emb, aW1, ab1, aW2, ab2);    // 6
    final_kernel<<<BP / 8, 256>>>(fW1, fb1, fW2, fb2, out); // 7
}

// round 11
// speedup vs baseline: 2.4590x; 2.4590x over previous
#include <cuda_runtime.h>
#include <math.h>
#include <cstdint>

// ---------------- problem constants ----------------
#define BN_ 16384
#define D_IN 1024
#define H1 512
#define H2 256
#define H3 128
#define FH 64
#define NDOM 4
#define EMB 16
#define BMROWS 128
#define BP 16896            // 132 tiles of 128 (>= 16384 + max padding 508)
#define NCB 64              // count blocks
#define NPERS 296           // persistent CTAs = 148 SMs x 2

// ---------------- scratch (device globals) ----------------
__device__ float g_norm[(size_t)BP * D_IN];
__device__ float g_h1c[(size_t)BP * H1];
__device__ float g_h1d[(size_t)BP * H1];
__device__ float g_h2c[(size_t)BP * H2];
__device__ float g_h2d[(size_t)BP * H2];
__device__ float g_h3c[(size_t)BP * H3];
__device__ float g_h3d[(size_t)BP * H3];
__device__ int   g_perm[BP];
__device__ int   g_bcnt[NCB][NDOM];
__device__ int   g_cnt[NDOM];
__device__ int   g_off[NDOM];
__device__ float g_aux[NDOM];

typedef unsigned long long u64;

// ---------------- f32x2 helpers ----------------
__device__ __forceinline__ u64 pack2(float x) {
    u64 r;
    asm("mov.b64 %0, {%1, %1};" : "=l"(r) : "r"(__float_as_uint(x)));
    return r;
}
__device__ __forceinline__ void fma2(u64& d, u64 a, u64 b) {
    asm("fma.rn.f32x2 %0, %1, %2, %0;" : "+l"(d) : "l"(a), "l"(b));
}
__device__ __forceinline__ float2 unpack2(u64 v) {
    uint32_t lo, hi;
    asm("mov.b64 {%0, %1}, %2;" : "=r"(lo), "=r"(hi) : "l"(v));
    float2 f;
    f.x = __uint_as_float(lo);
    f.y = __uint_as_float(hi);
    return f;
}

__device__ __forceinline__ uint32_t smem_u32(const void* p) {
    uint32_t a;
    asm("{ .reg .u64 t; cvta.to.shared.u64 t, %1; cvt.u32.u64 %0, t; }" : "=r"(a) : "l"(p));
    return a;
}
__device__ __forceinline__ void cp_async16(uint32_t dst, const void* src) {
    asm volatile("cp.async.ca.shared.global [%0], [%1], 16;"
                 :: "r"(dst), "l"(src) : "memory");
}
__device__ __forceinline__ void cp_commit() {
    asm volatile("cp.async.commit_group;" ::: "memory");
}
template <int N>
__device__ __forceinline__ void cp_wait() {
    asm volatile("cp.async.wait_group %0;" :: "n"(N) : "memory");
}

// pad region helpers
__device__ __forceinline__ int pad4(int c) { return (c + BMROWS - 1) & ~(BMROWS - 1); }

__device__ __forceinline__ int dom_of(int p) {
    int d = 0;
    #pragma unroll
    for (int k = 1; k < NDOM; k++) d += (p >= g_off[k]);
    return d;
}

// ---------------- sort: count (per-block partials) ----------------
__global__ __launch_bounds__(256) void count_kernel(const int* __restrict__ dids) {
    __shared__ int sc[NDOM];
    int tid = threadIdx.x;
    if (tid < NDOM) sc[tid] = 0;
    __syncthreads();
    int i = blockIdx.x * 256 + tid;
    atomicAdd(&sc[dids[i]], 1);
    __syncthreads();
    if (tid < NDOM) g_bcnt[blockIdx.x][tid] = sc[tid];
}

// ---------------- sort: scatter with inline prefix (publishes off/cnt) ----------------
__global__ __launch_bounds__(256) void scatter_kernel(const int* __restrict__ dids) {
    __shared__ int pre[NDOM];
    __shared__ int loc[NDOM];
    __shared__ int stot[NDOM], sbase[NDOM];
    int tid = threadIdx.x;
    if (tid < NDOM) {
        int d = tid, base = 0, tot = 0;
        #pragma unroll 8
        for (int b = 0; b < NCB; b++) {
            int c = g_bcnt[b][d];
            if (b < (int)blockIdx.x) base += c;
            tot += c;
        }
        stot[d] = tot; sbase[d] = base;
        loc[d] = 0;
    }
    __syncthreads();
    if (tid == 0) {
        int off = 0;
        #pragma unroll
        for (int d = 0; d < NDOM; d++) {
            pre[d] = off + sbase[d];
            if (blockIdx.x == 0) { g_off[d] = off; g_cnt[d] = stot[d]; }
            off += pad4(stot[d]);
        }
    }
    __syncthreads();
    int i = blockIdx.x * 256 + tid;
    int d = dids[i];
    int rank = atomicAdd(&loc[d], 1);
    g_perm[pre[d] + rank] = i;
}

// aux net (domain-only) -> 4 scalars
__global__ void aux_kernel(const float* __restrict__ dom_emb,
                           const float* __restrict__ aW1, const float* __restrict__ ab1,
                           const float* __restrict__ aW2, const float* __restrict__ ab2) {
    int w = threadIdx.x >> 5;
    int j = threadIdx.x & 31;
    float s = ab1[j];
    #pragma unroll
    for (int i = 0; i < EMB; i++) s += dom_emb[w * EMB + i] * aW1[i * 32 + j];
    float v = fmaxf(s, 0.f) * aW2[j];
    #pragma unroll
    for (int o = 16; o; o >>= 1) v += __shfl_xor_sync(0xFFFFFFFFu, v, o);
    if (j == 0) g_aux[w] = v + ab2[0];
}

// ---------------- layernorm + domain affine, permuted order ----------------
__global__ __launch_bounds__(256) void ln_kernel(const float* __restrict__ x,
                                                 const int* __restrict__ dids,
                                                 const float* __restrict__ pnw,
                                                 const float* __restrict__ pnb) {
    int p = blockIdx.x;
    int tid = threadIdx.x;
    float* out = g_norm + (size_t)p * D_IN;
    int d0 = dom_of(p);
    bool pad = (p - g_off[d0]) >= g_cnt[d0];
    if (pad) {
        float4 z = {0.f, 0.f, 0.f, 0.f};
        *(float4*)&out[tid * 4] = z;
        return;
    }
    int r = g_perm[p];
    const float* xr = x + (size_t)r * D_IN;
    float4 v = *(const float4*)&xr[tid * 4];
    float s = v.x + v.y + v.z + v.w;
    float q = v.x * v.x + v.y * v.y + v.z * v.z + v.w * v.w;
    #pragma unroll
    for (int o = 16; o; o >>= 1) {
        s += __shfl_xor_sync(0xFFFFFFFFu, s, o);
        q += __shfl_xor_sync(0xFFFFFFFFu, q, o);
    }
    __shared__ float ss[8], sq[8];
    __shared__ float smean, sinv;
    if ((tid & 31) == 0) { ss[tid >> 5] = s; sq[tid >> 5] = q; }
    __syncthreads();
    if (tid < 32) {
        s = (tid < 8) ? ss[tid] : 0.f;
        q = (tid < 8) ? sq[tid] : 0.f;
        #pragma unroll
        for (int o = 4; o; o >>= 1) {
            s += __shfl_xor_sync(0xFFFFFFFFu, s, o);
            q += __shfl_xor_sync(0xFFFFFFFFu, q, o);
        }
        if (tid == 0) {
            float mean = s * (1.f / D_IN);
            float var = q * (1.f / D_IN) - mean * mean;
            smean = mean;
            sinv = rsqrtf(var + 1e-5f);
        }
    }
    __syncthreads();
    int d = dids[r];
    float4 w = *(const float4*)&pnw[(size_t)d * D_IN + tid * 4];
    float4 b = *(const float4*)&pnb[(size_t)d * D_IN + tid * 4];
    float m = smean, inv = sinv;
    float4 o;
    o.x = (v.x - m) * inv * w.x + b.x;
    o.y = (v.y - m) * inv * w.y + b.y;
    o.z = (v.z - m) * inv * w.z + b.z;
    o.w = (v.w - m) * inv * w.w + b.w;
    *(float4*)&out[tid * 4] = o;
}

// ---------------- persistent tiled GEMM: BK=16, 4-stage B ring, race-free ----------------
// Grid = NPERS CTAs; each strides over the tile list. Per tile identical to R7's
// proven microkernel, but B uses a 4-stage cp.async ring so the pre-barrier issue
// of stage (t+2)%4 can never collide with the laggiest reader on stage (t-1)%4
// (distance 3). A: LDG->regs pre-barrier, STS-after-compute into 2-stage As.
// Tile-boundary safety: NT is even, so the old tile's last reads hit As stage 1 /
// Bs stage 3 while the new prologue writes As stage 0 / Bs stages 0,1.
template <int K, int N, bool RELU, int LAYER>
__global__ __launch_bounds__(256, 2) void gemm_kernel(const float* __restrict__ Wc,
                                                      const float* __restrict__ Wd,
                                                      const float* __restrict__ bc,
                                                      const float* __restrict__ bd) {
    constexpr int BM = 128, BNT = 128, BK = 16;
    constexpr int NX = N / BNT;
    constexpr int TT = NX * (BP / BMROWS) * 2;
    constexpr int NT = K / BK;
    __shared__ float As[2][BK][BM];    // 2 x 8KB
    __shared__ float Bs[4][BK][BNT];   // 4 x 8KB

    const int tid = threadIdx.x;
    const int tx = tid & 15, ty = tid >> 4;

    // loader coords
    const int ar0 = tid >> 2, ar1 = ar0 + 64;
    const int ac0 = (tid & 3) * 4;
    const int bk0 = tid >> 5;                 // 0..7 (+8 for second chunk)
    const int bn0 = (tid & 31) * 4;
    const uint32_t sBu = smem_u32(Bs);

    for (int tile = blockIdx.x; tile < TT; tile += NPERS) {
        // decode: bx fastest, then z, then by (consecutive tiles share A rows)
        const int bx = tile % NX;
        const int rest = tile / NX;
        const int z = rest & 1;
        const int by = rest >> 1;
        const int m0 = by * BM;
        const int n0 = bx * BNT;

        const float* A; float* C;
        if constexpr (LAYER == 1) { A = g_norm;               C = z ? g_h1d : g_h1c; }
        if constexpr (LAYER == 2) { A = z ? g_h1d : g_h1c;    C = z ? g_h2d : g_h2c; }
        if constexpr (LAYER == 3) { A = z ? g_h2d : g_h2c;    C = z ? g_h3d : g_h3c; }

        const float* W; const float* bias;
        if (z == 0) { W = Wc; bias = bc; }
        else {
            int dom = dom_of(m0);
            W = Wd + (size_t)dom * K * N;
            bias = bd + (size_t)dom * N;
        }

        u64 acc[8][4];
        #pragma unroll
        for (int i = 0; i < 8; i++)
            #pragma unroll
            for (int j = 0; j < 4; j++) acc[i][j] = 0ull;

        // B issue: tile kt -> stage kt%4
        auto issueB = [&](int kt) {
            uint32_t dst = sBu + (uint32_t)((kt & 3) * BK * BNT) * 4;
            const float* src = W + (size_t)kt * BK * N + n0 + bn0;
            cp_async16(dst + (bk0 * BNT + bn0) * 4,       src + (size_t)bk0 * N);
            cp_async16(dst + ((bk0 + 8) * BNT + bn0) * 4, src + (size_t)(bk0 + 8) * N);
            cp_commit();
        };
        auto ldgA = [&](int kt, float4* av) {
            const float* src = A + (size_t)m0 * K + kt * BK;
            av[0] = *(const float4*)&src[(size_t)ar0 * K + ac0];
            av[1] = *(const float4*)&src[(size_t)ar1 * K + ac0];
        };
        auto stsA = [&](int st, const float4* av) {
            As[st][ac0 + 0][ar0] = av[0].x;
            As[st][ac0 + 1][ar0] = av[0].y;
            As[st][ac0 + 2][ar0] = av[0].z;
            As[st][ac0 + 3][ar0] = av[0].w;
            As[st][ac0 + 0][ar1] = av[1].x;
            As[st][ac0 + 1][ar1] = av[1].y;
            As[st][ac0 + 2][ar1] = av[1].z;
            As[st][ac0 + 3][ar1] = av[1].w;
        };

        // prologue (safe vs lagging warps of previous tile: they read As stage 1 /
        // Bs stage 3 only; we write As stage 0, Bs stages 0,1)
        float4 av[2];
        ldgA(0, av);
        issueB(0);
        issueB(1);
        stsA(0, av);

        for (int t = 0; t < NT; t++) {
            const int s = t & 1;
            if (t + 1 < NT) ldgA(t + 1, av);        // private regs, race-free
            if (t + 2 < NT) issueB(t + 2);          // stage (t+2)%4, distance-3 safe
            if (t + 2 < NT)      { cp_wait<2>(); }
            else if (t + 1 < NT) { cp_wait<1>(); }
            else                 { cp_wait<0>(); }
            __syncthreads();

            #pragma unroll
            for (int kk = 0; kk < BK; kk++) {
                float a[8];
                *(float4*)&a[0] = *(const float4*)&As[s][kk][ty * 4];
                *(float4*)&a[4] = *(const float4*)&As[s][kk][ty * 4 + 64];
                const u64* bp0 = (const u64*)&Bs[t & 3][kk][tx * 4];
                const u64* bp1 = (const u64*)&Bs[t & 3][kk][tx * 4 + 64];
                u64 b0 = bp0[0], b1 = bp0[1], b2 = bp1[0], b3 = bp1[1];
                #pragma unroll
                for (int i = 0; i < 8; i++) {
                    u64 ai = pack2(a[i]);
                    fma2(acc[i][0], ai, b0);
                    fma2(acc[i][1], ai, b1);
                    fma2(acc[i][2], ai, b2);
                    fma2(acc[i][3], ai, b3);
                }
            }

            if (t + 1 < NT) stsA(s ^ 1, av);        // after compute: safe
        }

        float bj[8];
        #pragma unroll
        for (int j = 0; j < 8; j++) {
            int cn = tx * 4 + (j & 3) + ((j >> 2) * 64);
            bj[j] = bias[n0 + cn];
        }
        #pragma unroll
        for (int i = 0; i < 8; i++) {
            int m = m0 + ty * 4 + (i & 3) + ((i >> 2) * 64);
            float2 c0 = unpack2(acc[i][0]);
            float2 c1 = unpack2(acc[i][1]);
            float2 c2 = unpack2(acc[i][2]);
            float2 c3 = unpack2(acc[i][3]);
            float4 o0, o1;
            o0.x = c0.x + bj[0]; o0.y = c0.y + bj[1];
            o0.z = c1.x + bj[2]; o0.w = c1.y + bj[3];
            o1.x = c2.x + bj[4]; o1.y = c2.y + bj[5];
            o1.z = c3.x + bj[6]; o1.w = c3.y + bj[7];
            if (RELU) {
                o0.x = fmaxf(o0.x, 0.f); o0.y = fmaxf(o0.y, 0.f);
                o0.z = fmaxf(o0.z, 0.f); o0.w = fmaxf(o0.w, 0.f);
                o1.x = fmaxf(o1.x, 0.f); o1.y = fmaxf(o1.y, 0.f);
                o1.z = fmaxf(o1.z, 0.f); o1.w = fmaxf(o1.w, 0.f);
            }
            *(float4*)&C[(size_t)m * N + n0 + tx * 4]      = o0;
            *(float4*)&C[(size_t)m * N + n0 + tx * 4 + 64] = o1;
        }
    }
}

// ---------------- fuse + final MLP + aux + sigmoid (one warp per row) ----------------
__global__ __launch_bounds__(256) void final_kernel(const float* __restrict__ fW1,
                                                    const float* __restrict__ fb1,
                                                    const float* __restrict__ fW2,
                                                    const float* __restrict__ fb2,
                                                    float* __restrict__ out) {
    __shared__ float sW1[H3 * FH];
    __shared__ float sb1[FH], sW2[FH];
    __shared__ float sf[8][H3];

    int tid = threadIdx.x;
    for (int i = tid; i < H3 * FH; i += 256) sW1[i] = fW1[i];
    if (tid < FH) { sb1[tid] = fb1[tid]; sW2[tid] = fW2[tid]; }
    __syncthreads();

    int w = tid >> 5, lane = tid & 31;
    int p = blockIdx.x * 8 + w;
    int d0 = dom_of(p);
    bool pad = (p - g_off[d0]) >= g_cnt[d0];

    #pragma unroll
    for (int q = 0; q < 4; q++) {
        int i = q * 32 + lane;
        float c = g_h3c[(size_t)p * H3 + i];
        float d = g_h3d[(size_t)p * H3 + i];
        sf[w][i] = c * tanhf(d);
    }
    __syncwarp();

    float acc = 0.f;
    #pragma unroll
    for (int jj = 0; jj < 2; jj++) {
        int j = jj * 32 + lane;
        float h = sb1[j];
        #pragma unroll 8
        for (int i = 0; i < H3; i++) h += sf[w][i] * sW1[i * FH + j];
        acc += fmaxf(h, 0.f) * sW2[j];
    }
    #pragma unroll
    for (int o = 16; o; o >>= 1) acc += __shfl_xor_sync(0xFFFFFFFFu, acc, o);

    if (lane == 0 && !pad) {
        int r = g_perm[p];
        float v = acc + fb2[0] + g_aux[d0];
        out[r] = 1.f / (1.f + expf(-v));
    }
}

// ---------------- launch ----------------
extern "C" void kernel_launch(void* const* d_in, const int* in_sizes, int n_in,
                              void* d_out, int out_size) {
    const float* x      = (const float*)d_in[0];
    const int*   dids   = (const int*)  d_in[1];
    const float* pnw    = (const float*)d_in[2];
    const float* pnb    = (const float*)d_in[3];
    const float* cW1    = (const float*)d_in[4];
    const float* cb1    = (const float*)d_in[5];
    const float* cW2    = (const float*)d_in[6];
    const float* cb2    = (const float*)d_in[7];
    const float* cW3    = (const float*)d_in[8];
    const float* cb3    = (const float*)d_in[9];
    const float* dW1    = (const float*)d_in[10];
    const float* db1    = (const float*)d_in[11];
    const float* dW2    = (const float*)d_in[12];
    const float* db2    = (const float*)d_in[13];
    const float* dW3    = (const float*)d_in[14];
    const float* db3    = (const float*)d_in[15];
    const float* fW1    = (const float*)d_in[16];
    const float* fb1    = (const float*)d_in[17];
    const float* fW2    = (const float*)d_in[18];
    const float* fb2    = (const float*)d_in[19];
    const float* dom_emb= (const float*)d_in[20];
    const float* aW1    = (const float*)d_in[21];
    const float* ab1    = (const float*)d_in[22];
    const float* aW2    = (const float*)d_in[23];
    const float* ab2    = (const float*)d_in[24];
    float* out = (float*)d_out;

    count_kernel<<<NCB, 256>>>(dids);                 // 0
    scatter_kernel<<<NCB, 256>>>(dids);               // 1
    ln_kernel<<<BP, 256>>>(x, dids, pnw, pnb);        // 2

    gemm_kernel<D_IN, H1, true,  1><<<NPERS, 256>>>(cW1, dW1, cb1, db1);  // 3
    gemm_kernel<H1,   H2, true,  2><<<NPERS, 256>>>(cW2, dW2, cb2, db2);  // 4
    gemm_kernel<H2,   H3, false, 3><<<NPERS, 256>>>(cW3, dW3, cb3, db3);  // 5

    aux_kernel<<<1, 128>>>(dom_emb, aW1, ab1, aW2, ab2);    // 6
    final_kernel<<<BP / 8, 256>>>(fW1, fb1, fW2, fb2, out); // 7
}

// round 12
// speedup vs baseline: 2.8067x; 1.1414x over previous
#include <cuda_runtime.h>
#include <math.h>
#include <cstdint>

// ---------------- problem constants ----------------
#define BN_ 16384
#define D_IN 1024
#define H1 512
#define H2 256
#define H3 128
#define FH 64
#define NDOM 4
#define EMB 16
#define BMROWS 128
#define BP 16896            // 132 tiles of 128 (>= 16384 + max padding 508)
#define NCB 64              // count blocks

// ---------------- scratch (device globals) ----------------
__device__ float g_norm[(size_t)BP * D_IN];
__device__ float g_h1c[(size_t)BP * H1];
__device__ float g_h1d[(size_t)BP * H1];
__device__ float g_h2c[(size_t)BP * H2];
__device__ float g_h2d[(size_t)BP * H2];
__device__ float g_h3c[(size_t)BP * H3];
__device__ float g_h3d[(size_t)BP * H3];
__device__ int   g_perm[BP];
__device__ int   g_bcnt[NCB][NDOM];
__device__ int   g_cnt[NDOM];
__device__ int   g_off[NDOM];
__device__ float g_aux[NDOM];

typedef unsigned long long u64;

// ---------------- f32x2 helpers ----------------
__device__ __forceinline__ u64 pack2(float x) {
    u64 r;
    asm("mov.b64 %0, {%1, %1};" : "=l"(r) : "r"(__float_as_uint(x)));
    return r;
}
__device__ __forceinline__ void fma2(u64& d, u64 a, u64 b) {
    asm("fma.rn.f32x2 %0, %1, %2, %0;" : "+l"(d) : "l"(a), "l"(b));
}
__device__ __forceinline__ float2 unpack2(u64 v) {
    uint32_t lo, hi;
    asm("mov.b64 {%0, %1}, %2;" : "=r"(lo), "=r"(hi) : "l"(v));
    float2 f;
    f.x = __uint_as_float(lo);
    f.y = __uint_as_float(hi);
    return f;
}

__device__ __forceinline__ uint32_t smem_u32(const void* p) {
    uint32_t a;
    asm("{ .reg .u64 t; cvta.to.shared.u64 t, %1; cvt.u32.u64 %0, t; }" : "=r"(a) : "l"(p));
    return a;
}
__device__ __forceinline__ void cp_async16(uint32_t dst, const void* src) {
    asm volatile("cp.async.ca.shared.global [%0], [%1], 16;"
                 :: "r"(dst), "l"(src) : "memory");
}
__device__ __forceinline__ void cp_commit() {
    asm volatile("cp.async.commit_group;" ::: "memory");
}
template <int N>
__device__ __forceinline__ void cp_wait() {
    asm volatile("cp.async.wait_group %0;" :: "n"(N) : "memory");
}

// pad region helpers
__device__ __forceinline__ int pad4(int c) { return (c + BMROWS - 1) & ~(BMROWS - 1); }

__device__ __forceinline__ int dom_of(int p) {
    int d = 0;
    #pragma unroll
    for (int k = 1; k < NDOM; k++) d += (p >= g_off[k]);
    return d;
}

// ---------------- sort: count (per-block partials) ----------------
__global__ __launch_bounds__(256) void count_kernel(const int* __restrict__ dids) {
    __shared__ int sc[NDOM];
    int tid = threadIdx.x;
    if (tid < NDOM) sc[tid] = 0;
    __syncthreads();
    int i = blockIdx.x * 256 + tid;
    atomicAdd(&sc[dids[i]], 1);
    __syncthreads();
    if (tid < NDOM) g_bcnt[blockIdx.x][tid] = sc[tid];
}

// ---------------- sort: scatter with inline prefix (publishes off/cnt) ----------------
__global__ __launch_bounds__(256) void scatter_kernel(const int* __restrict__ dids) {
    __shared__ int pre[NDOM];
    __shared__ int loc[NDOM];
    __shared__ int stot[NDOM], sbase[NDOM];
    int tid = threadIdx.x;
    if (tid < NDOM) {
        int d = tid, base = 0, tot = 0;
        #pragma unroll 8
        for (int b = 0; b < NCB; b++) {
            int c = g_bcnt[b][d];
            if (b < (int)blockIdx.x) base += c;
            tot += c;
        }
        stot[d] = tot; sbase[d] = base;
        loc[d] = 0;
    }
    __syncthreads();
    if (tid == 0) {
        int off = 0;
        #pragma unroll
        for (int d = 0; d < NDOM; d++) {
            pre[d] = off + sbase[d];
            if (blockIdx.x == 0) { g_off[d] = off; g_cnt[d] = stot[d]; }
            off += pad4(stot[d]);
        }
    }
    __syncthreads();
    int i = blockIdx.x * 256 + tid;
    int d = dids[i];
    int rank = atomicAdd(&loc[d], 1);
    g_perm[pre[d] + rank] = i;
}

// aux net (domain-only) -> 4 scalars
__global__ void aux_kernel(const float* __restrict__ dom_emb,
                           const float* __restrict__ aW1, const float* __restrict__ ab1,
                           const float* __restrict__ aW2, const float* __restrict__ ab2) {
    int w = threadIdx.x >> 5;
    int j = threadIdx.x & 31;
    float s = ab1[j];
    #pragma unroll
    for (int i = 0; i < EMB; i++) s += dom_emb[w * EMB + i] * aW1[i * 32 + j];
    float v = fmaxf(s, 0.f) * aW2[j];
    #pragma unroll
    for (int o = 16; o; o >>= 1) v += __shfl_xor_sync(0xFFFFFFFFu, v, o);
    if (j == 0) g_aux[w] = v + ab2[0];
}

// ---------------- layernorm + domain affine, permuted order ----------------
__global__ __launch_bounds__(256) void ln_kernel(const float* __restrict__ x,
                                                 const int* __restrict__ dids,
                                                 const float* __restrict__ pnw,
                                                 const float* __restrict__ pnb) {
    int p = blockIdx.x;
    int tid = threadIdx.x;
    float* out = g_norm + (size_t)p * D_IN;
    int d0 = dom_of(p);
    bool pad = (p - g_off[d0]) >= g_cnt[d0];
    if (pad) {
        float4 z = {0.f, 0.f, 0.f, 0.f};
        *(float4*)&out[tid * 4] = z;
        return;
    }
    int r = g_perm[p];
    const float* xr = x + (size_t)r * D_IN;
    float4 v = *(const float4*)&xr[tid * 4];
    float s = v.x + v.y + v.z + v.w;
    float q = v.x * v.x + v.y * v.y + v.z * v.z + v.w * v.w;
    #pragma unroll
    for (int o = 16; o; o >>= 1) {
        s += __shfl_xor_sync(0xFFFFFFFFu, s, o);
        q += __shfl_xor_sync(0xFFFFFFFFu, q, o);
    }
    __shared__ float ss[8], sq[8];
    __shared__ float smean, sinv;
    if ((tid & 31) == 0) { ss[tid >> 5] = s; sq[tid >> 5] = q; }
    __syncthreads();
    if (tid < 32) {
        s = (tid < 8) ? ss[tid] : 0.f;
        q = (tid < 8) ? sq[tid] : 0.f;
        #pragma unroll
        for (int o = 4; o; o >>= 1) {
            s += __shfl_xor_sync(0xFFFFFFFFu, s, o);
            q += __shfl_xor_sync(0xFFFFFFFFu, q, o);
        }
        if (tid == 0) {
            float mean = s * (1.f / D_IN);
            float var = q * (1.f / D_IN) - mean * mean;
            smean = mean;
            sinv = rsqrtf(var + 1e-5f);
        }
    }
    __syncthreads();
    int d = dids[r];
    float4 w = *(const float4*)&pnw[(size_t)d * D_IN + tid * 4];
    float4 b = *(const float4*)&pnb[(size_t)d * D_IN + tid * 4];
    float m = smean, inv = sinv;
    float4 o;
    o.x = (v.x - m) * inv * w.x + b.x;
    o.y = (v.y - m) * inv * w.y + b.y;
    o.z = (v.z - m) * inv * w.z + b.z;
    o.w = (v.w - m) * inv * w.w + b.w;
    *(float4*)&out[tid * 4] = o;
}

// ---------------- tiled GEMM v6: R7 pipeline + 3-stage B ring (race-free) ----------------
// BK=16, issue-ahead-1, cp_wait<1>, one __syncthreads per k-tile.
// B ring: writer at iter t targets stage (t+1)%3; laggiest reader is on (t-1)%3,
// distance 2 (mod 3 != 0) -> no collision. A: LDG->regs pre-barrier,
// STS-after-compute into 2-stage As (readers of target stage passed barrier(t)).
template <int K, int N, bool RELU, int LAYER>
__global__ __launch_bounds__(256, 2) void gemm_kernel(const float* __restrict__ Wc,
                                                      const float* __restrict__ Wd,
                                                      const float* __restrict__ bc,
                                                      const float* __restrict__ bd) {
    constexpr int BM = 128, BNT = 128, BK = 16;
    __shared__ float As[2][BK][BM];    // 16KB
    __shared__ float Bs[3][BK][BNT];   // 24KB

    const int tid = threadIdx.x;
    const int tx = tid & 15, ty = tid >> 4;
    const int by = blockIdx.y, bx = blockIdx.x;
    const int z = blockIdx.z;
    const int m0 = by * BM;
    const int n0 = bx * BNT;

    const float* A; float* C;
    if constexpr (LAYER == 1) { A = g_norm;               C = z ? g_h1d : g_h1c; }
    if constexpr (LAYER == 2) { A = z ? g_h1d : g_h1c;    C = z ? g_h2d : g_h2c; }
    if constexpr (LAYER == 3) { A = z ? g_h2d : g_h2c;    C = z ? g_h3d : g_h3c; }

    const float* W; const float* bias;
    if (z == 0) { W = Wc; bias = bc; }
    else {
        int dom = dom_of(m0);
        W = Wd + (size_t)dom * K * N;
        bias = bd + (size_t)dom * N;
    }

    // loader coords
    const int ar0 = tid >> 2, ar1 = ar0 + 64;
    const int ac0 = (tid & 3) * 4;
    const int bk0 = tid >> 5;                 // 0..7 (+8 for second chunk)
    const int bn0 = (tid & 31) * 4;
    const uint32_t sBu = smem_u32(Bs);

    u64 acc[8][4];
    #pragma unroll
    for (int i = 0; i < 8; i++)
        #pragma unroll
        for (int j = 0; j < 4; j++) acc[i][j] = 0ull;

    constexpr int NT = K / BK;

    auto issueB = [&](int kt, int st) {       // k-tile kt -> ring stage st
        uint32_t dst = sBu + (uint32_t)(st * BK * BNT) * 4;
        const float* src = W + (size_t)kt * BK * N + n0 + bn0;
        cp_async16(dst + (bk0 * BNT + bn0) * 4,       src + (size_t)bk0 * N);
        cp_async16(dst + ((bk0 + 8) * BNT + bn0) * 4, src + (size_t)(bk0 + 8) * N);
        cp_commit();
    };
    auto ldgA = [&](int kt, float4* av) {
        const float* src = A + (size_t)m0 * K + kt * BK;
        av[0] = *(const float4*)&src[(size_t)ar0 * K + ac0];
        av[1] = *(const float4*)&src[(size_t)ar1 * K + ac0];
    };
    auto stsA = [&](int st, const float4* av) {
        As[st][ac0 + 0][ar0] = av[0].x;
        As[st][ac0 + 1][ar0] = av[0].y;
        As[st][ac0 + 2][ar0] = av[0].z;
        As[st][ac0 + 3][ar0] = av[0].w;
        As[st][ac0 + 0][ar1] = av[1].x;
        As[st][ac0 + 1][ar1] = av[1].y;
        As[st][ac0 + 2][ar1] = av[1].z;
        As[st][ac0 + 3][ar1] = av[1].w;
    };

    // prologue: A(0) -> As[0]; B(0) -> stage 0
    float4 av[2];
    ldgA(0, av);
    issueB(0, 0);
    stsA(0, av);

    int rd_st = 0;                 // ring stage of tile t
    for (int t = 0; t < NT; t++) {
        const int s = t & 1;
        const int wr_st = (rd_st == 2) ? 0 : rd_st + 1;
        if (t + 1 < NT) {
            ldgA(t + 1, av);                  // private regs, race-free
            issueB(t + 1, wr_st);             // stage distance 2 from laggards
            cp_wait<1>();
        } else {
            cp_wait<0>();
        }
        __syncthreads();

        #pragma unroll
        for (int kk = 0; kk < BK; kk++) {
            float a[8];
            *(float4*)&a[0] = *(const float4*)&As[s][kk][ty * 4];
            *(float4*)&a[4] = *(const float4*)&As[s][kk][ty * 4 + 64];
            uint4 bq0 = *(const uint4*)&Bs[rd_st][kk][tx * 4];
            uint4 bq1 = *(const uint4*)&Bs[rd_st][kk][tx * 4 + 64];
            u64 b0 = ((const u64*)&bq0)[0], b1 = ((const u64*)&bq0)[1];
            u64 b2 = ((const u64*)&bq1)[0], b3 = ((const u64*)&bq1)[1];
            #pragma unroll
            for (int i = 0; i < 8; i++) {
                u64 ai = pack2(a[i]);
                fma2(acc[i][0], ai, b0);
                fma2(acc[i][1], ai, b1);
                fma2(acc[i][2], ai, b2);
                fma2(acc[i][3], ai, b3);
            }
        }

        if (t + 1 < NT) stsA(s ^ 1, av);      // after compute: safe
        rd_st = wr_st;
    }

    float bj[8];
    #pragma unroll
    for (int j = 0; j < 8; j++) {
        int cn = tx * 4 + (j & 3) + ((j >> 2) * 64);
        bj[j] = bias[n0 + cn];
    }
    #pragma unroll
    for (int i = 0; i < 8; i++) {
        int m = m0 + ty * 4 + (i & 3) + ((i >> 2) * 64);
        float2 c0 = unpack2(acc[i][0]);
        float2 c1 = unpack2(acc[i][1]);
        float2 c2 = unpack2(acc[i][2]);
        float2 c3 = unpack2(acc[i][3]);
        float4 o0, o1;
        o0.x = c0.x + bj[0]; o0.y = c0.y + bj[1];
        o0.z = c1.x + bj[2]; o0.w = c1.y + bj[3];
        o1.x = c2.x + bj[4]; o1.y = c2.y + bj[5];
        o1.z = c3.x + bj[6]; o1.w = c3.y + bj[7];
        if (RELU) {
            o0.x = fmaxf(o0.x, 0.f); o0.y = fmaxf(o0.y, 0.f);
            o0.z = fmaxf(o0.z, 0.f); o0.w = fmaxf(o0.w, 0.f);
            o1.x = fmaxf(o1.x, 0.f); o1.y = fmaxf(o1.y, 0.f);
            o1.z = fmaxf(o1.z, 0.f); o1.w = fmaxf(o1.w, 0.f);
        }
        *(float4*)&C[(size_t)m * N + n0 + tx * 4]      = o0;
        *(float4*)&C[(size_t)m * N + n0 + tx * 4 + 64] = o1;
    }
}

// ---------------- fuse + final MLP + aux + sigmoid ----------------
// 32 rows per block in 4 groups of 8 (reuses the 32KB fW1 smem image 4x).
__global__ __launch_bounds__(256) void final_kernel(const float* __restrict__ fW1,
                                                    const float* __restrict__ fb1,
                                                    const float* __restrict__ fW2,
                                                    const float* __restrict__ fb2,
                                                    float* __restrict__ out) {
    __shared__ float sW1[H3 * FH];
    __shared__ float sb1[FH], sW2[FH];
    __shared__ float sf[8][H3];

    int tid = threadIdx.x;
    for (int i = tid; i < H3 * FH; i += 256) sW1[i] = fW1[i];
    if (tid < FH) { sb1[tid] = fb1[tid]; sW2[tid] = fW2[tid]; }
    __syncthreads();

    int w = tid >> 5, lane = tid & 31;

    #pragma unroll
    for (int grp = 0; grp < 4; grp++) {
        int p = blockIdx.x * 32 + grp * 8 + w;
        int d0 = dom_of(p);
        bool pad = (p - g_off[d0]) >= g_cnt[d0];

        #pragma unroll
        for (int q = 0; q < 4; q++) {
            int i = q * 32 + lane;
            float c = g_h3c[(size_t)p * H3 + i];
            float d = g_h3d[(size_t)p * H3 + i];
            sf[w][i] = c * tanhf(d);
        }
        __syncwarp();

        float acc = 0.f;
        #pragma unroll
        for (int jj = 0; jj < 2; jj++) {
            int j = jj * 32 + lane;
            float h = sb1[j];
            #pragma unroll 8
            for (int i = 0; i < H3; i++) h += sf[w][i] * sW1[i * FH + j];
            acc += fmaxf(h, 0.f) * sW2[j];
        }
        #pragma unroll
        for (int o = 16; o; o >>= 1) acc += __shfl_xor_sync(0xFFFFFFFFu, acc, o);

        if (lane == 0 && !pad) {
            int r = g_perm[p];
            float v = acc + fb2[0] + g_aux[d0];
            out[r] = 1.f / (1.f + expf(-v));
        }
        __syncwarp();
    }
}

// ---------------- launch ----------------
extern "C" void kernel_launch(void* const* d_in, const int* in_sizes, int n_in,
                              void* d_out, int out_size) {
    const float* x      = (const float*)d_in[0];
    const int*   dids   = (const int*)  d_in[1];
    const float* pnw    = (const float*)d_in[2];
    const float* pnb    = (const float*)d_in[3];
    const float* cW1    = (const float*)d_in[4];
    const float* cb1    = (const float*)d_in[5];
    const float* cW2    = (const float*)d_in[6];
    const float* cb2    = (const float*)d_in[7];
    const float* cW3    = (const float*)d_in[8];
    const float* cb3    = (const float*)d_in[9];
    const float* dW1    = (const float*)d_in[10];
    const float* db1    = (const float*)d_in[11];
    const float* dW2    = (const float*)d_in[12];
    const float* db2    = (const float*)d_in[13];
    const float* dW3    = (const float*)d_in[14];
    const float* db3    = (const float*)d_in[15];
    const float* fW1    = (const float*)d_in[16];
    const float* fb1    = (const float*)d_in[17];
    const float* fW2    = (const float*)d_in[18];
    const float* fb2    = (const float*)d_in[19];
    const float* dom_emb= (const float*)d_in[20];
    const float* aW1    = (const float*)d_in[21];
    const float* ab1    = (const float*)d_in[22];
    const float* aW2    = (const float*)d_in[23];
    const float* ab2    = (const float*)d_in[24];
    float* out = (float*)d_out;

    count_kernel<<<NCB, 256>>>(dids);                 // 0
    scatter_kernel<<<NCB, 256>>>(dids);               // 1
    ln_kernel<<<BP, 256>>>(x, dids, pnw, pnb);        // 2

    gemm_kernel<D_IN, H1, true,  1>                   // 3
        <<<dim3(H1 / 128, BP / 128, 2), 256>>>(cW1, dW1, cb1, db1);
    gemm_kernel<H1,   H2, true,  2>                   // 4
        <<<dim3(H2 / 128, BP / 128, 2), 256>>>(cW2, dW2, cb2, db2);
    gemm_kernel<H2,   H3, false, 3>                   // 5
        <<<dim3(H3 / 128, BP / 128, 2), 256>>>(cW3, dW3, cb3, db3);

    aux_kernel<<<1, 128>>>(dom_emb, aW1, ab1, aW2, ab2);     // 6
    final_kernel<<<BP / 32, 256>>>(fW1, fb1, fW2, fb2, out); // 7
}

// round 14
// speedup vs baseline: 2.8731x; 1.0237x over previous
#include <cuda_runtime.h>
#include <math.h>
#include <cstdint>

// ---------------- problem constants ----------------
#define BN_ 16384
#define D_IN 1024
#define H1 512
#define H2 256
#define H3 128
#define FH 64
#define NDOM 4
#define EMB 16
#define BMROWS 128
#define BP 16896            // 132 tiles of 128 (>= 16384 + max padding 508)
#define NCB 64              // count blocks

// ---------------- scratch (device globals) ----------------
__device__ float g_norm[(size_t)BP * D_IN];
__device__ float g_h1c[(size_t)BP * H1];
__device__ float g_h1d[(size_t)BP * H1];
__device__ float g_h2c[(size_t)BP * H2];
__device__ float g_h2d[(size_t)BP * H2];
__device__ float g_h3c[(size_t)BP * H3];
__device__ float g_h3d[(size_t)BP * H3];
__device__ int   g_perm[BP];
__device__ int   g_bcnt[NCB][NDOM];
__device__ int   g_cnt[NDOM];
__device__ int   g_off[NDOM];
__device__ float g_aux[NDOM];

typedef unsigned long long u64;

// ---------------- f32x2 helpers ----------------
__device__ __forceinline__ u64 pack2(float x) {
    u64 r;
    asm("mov.b64 %0, {%1, %1};" : "=l"(r) : "r"(__float_as_uint(x)));
    return r;
}
__device__ __forceinline__ void fma2(u64& d, u64 a, u64 b) {
    asm("fma.rn.f32x2 %0, %1, %2, %0;" : "+l"(d) : "l"(a), "l"(b));
}
__device__ __forceinline__ float2 unpack2(u64 v) {
    uint32_t lo, hi;
    asm("mov.b64 {%0, %1}, %2;" : "=r"(lo), "=r"(hi) : "l"(v));
    float2 f;
    f.x = __uint_as_float(lo);
    f.y = __uint_as_float(hi);
    return f;
}

__device__ __forceinline__ uint32_t smem_u32(const void* p) {
    uint32_t a;
    asm("{ .reg .u64 t; cvta.to.shared.u64 t, %1; cvt.u32.u64 %0, t; }" : "=r"(a) : "l"(p));
    return a;
}
__device__ __forceinline__ void cp_async16(uint32_t dst, const void* src) {
    asm volatile("cp.async.ca.shared.global [%0], [%1], 16;"
                 :: "r"(dst), "l"(src) : "memory");
}
__device__ __forceinline__ void cp_commit() {
    asm volatile("cp.async.commit_group;" ::: "memory");
}
template <int N>
__device__ __forceinline__ void cp_wait() {
    asm volatile("cp.async.wait_group %0;" :: "n"(N) : "memory");
}

// pad region helpers
__device__ __forceinline__ int pad4(int c) { return (c + BMROWS - 1) & ~(BMROWS - 1); }

__device__ __forceinline__ int dom_of(int p) {
    int d = 0;
    #pragma unroll
    for (int k = 1; k < NDOM; k++) d += (p >= g_off[k]);
    return d;
}

// ---------------- sort: count (per-block partials) ----------------
__global__ __launch_bounds__(256) void count_kernel(const int* __restrict__ dids) {
    __shared__ int sc[NDOM];
    int tid = threadIdx.x;
    if (tid < NDOM) sc[tid] = 0;
    __syncthreads();
    int i = blockIdx.x * 256 + tid;
    atomicAdd(&sc[dids[i]], 1);
    __syncthreads();
    if (tid < NDOM) g_bcnt[blockIdx.x][tid] = sc[tid];
}

// ---------------- sort: scatter with inline prefix (publishes off/cnt) ----------------
__global__ __launch_bounds__(256) void scatter_kernel(const int* __restrict__ dids) {
    __shared__ int pre[NDOM];
    __shared__ int loc[NDOM];
    __shared__ int stot[NDOM], sbase[NDOM];
    int tid = threadIdx.x;
    if (tid < NDOM) {
        int d = tid, base = 0, tot = 0;
        #pragma unroll 8
        for (int b = 0; b < NCB; b++) {
            int c = g_bcnt[b][d];
            if (b < (int)blockIdx.x) base += c;
            tot += c;
        }
        stot[d] = tot; sbase[d] = base;
        loc[d] = 0;
    }
    __syncthreads();
    if (tid == 0) {
        int off = 0;
        #pragma unroll
        for (int d = 0; d < NDOM; d++) {
            pre[d] = off + sbase[d];
            if (blockIdx.x == 0) { g_off[d] = off; g_cnt[d] = stot[d]; }
            off += pad4(stot[d]);
        }
    }
    __syncthreads();
    int i = blockIdx.x * 256 + tid;
    int d = dids[i];
    int rank = atomicAdd(&loc[d], 1);
    g_perm[pre[d] + rank] = i;
}

// aux net (domain-only) -> 4 scalars
__global__ void aux_kernel(const float* __restrict__ dom_emb,
                           const float* __restrict__ aW1, const float* __restrict__ ab1,
                           const float* __restrict__ aW2, const float* __restrict__ ab2) {
    int w = threadIdx.x >> 5;
    int j = threadIdx.x & 31;
    float s = ab1[j];
    #pragma unroll
    for (int i = 0; i < EMB; i++) s += dom_emb[w * EMB + i] * aW1[i * 32 + j];
    float v = fmaxf(s, 0.f) * aW2[j];
    #pragma unroll
    for (int o = 16; o; o >>= 1) v += __shfl_xor_sync(0xFFFFFFFFu, v, o);
    if (j == 0) g_aux[w] = v + ab2[0];
}

// ---------------- layernorm + domain affine, permuted order ----------------
__global__ __launch_bounds__(256) void ln_kernel(const float* __restrict__ x,
                                                 const int* __restrict__ dids,
                                                 const float* __restrict__ pnw,
                                                 const float* __restrict__ pnb) {
    int p = blockIdx.x;
    int tid = threadIdx.x;
    float* out = g_norm + (size_t)p * D_IN;
    int d0 = dom_of(p);
    bool pad = (p - g_off[d0]) >= g_cnt[d0];
    if (pad) {
        float4 z = {0.f, 0.f, 0.f, 0.f};
        *(float4*)&out[tid * 4] = z;
        return;
    }
    int r = g_perm[p];
    const float* xr = x + (size_t)r * D_IN;
    float4 v = *(const float4*)&xr[tid * 4];
    float s = v.x + v.y + v.z + v.w;
    float q = v.x * v.x + v.y * v.y + v.z * v.z + v.w * v.w;
    #pragma unroll
    for (int o = 16; o; o >>= 1) {
        s += __shfl_xor_sync(0xFFFFFFFFu, s, o);
        q += __shfl_xor_sync(0xFFFFFFFFu, q, o);
    }
    __shared__ float ss[8], sq[8];
    __shared__ float smean, sinv;
    if ((tid & 31) == 0) { ss[tid >> 5] = s; sq[tid >> 5] = q; }
    __syncthreads();
    if (tid < 32) {
        s = (tid < 8) ? ss[tid] : 0.f;
        q = (tid < 8) ? sq[tid] : 0.f;
        #pragma unroll
        for (int o = 4; o; o >>= 1) {
            s += __shfl_xor_sync(0xFFFFFFFFu, s, o);
            q += __shfl_xor_sync(0xFFFFFFFFu, q, o);
        }
        if (tid == 0) {
            float mean = s * (1.f / D_IN);
            float var = q * (1.f / D_IN) - mean * mean;
            smean = mean;
            sinv = rsqrtf(var + 1e-5f);
        }
    }
    __syncthreads();
    int d = dids[r];
    float4 w = *(const float4*)&pnw[(size_t)d * D_IN + tid * 4];
    float4 b = *(const float4*)&pnb[(size_t)d * D_IN + tid * 4];
    float m = smean, inv = sinv;
    float4 o;
    o.x = (v.x - m) * inv * w.x + b.x;
    o.y = (v.y - m) * inv * w.y + b.y;
    o.z = (v.z - m) * inv * w.z + b.z;
    o.w = (v.w - m) * inv * w.w + b.w;
    *(float4*)&out[tid * 4] = o;
}

// ---------------- tiled GEMM v7: 4-stage B ring, compile-time stages ----------------
// R7 pipeline shape (BK=16, issue-ahead-1, cp_wait<1>, 1 barrier/tile) but with a
// 4-stage B ring and the k-tile loop unrolled by 4 so ALL ring/stage indices are
// compile-time immediates (kills the IMAD address chains seen in R11: alu 12%).
// Race-free: writer at iter t targets stage (t+1)%4; laggiest reader (one barrier
// behind) is on (t-1)%4 -> distance 2 mod 4 != 0. A: LDG->regs pre-barrier,
// STS-after-compute into As[t&1].
template <int K, int N, bool RELU, int LAYER>
__global__ __launch_bounds__(256, 2) void gemm_kernel(const float* __restrict__ Wc,
                                                      const float* __restrict__ Wd,
                                                      const float* __restrict__ bc,
                                                      const float* __restrict__ bd) {
    constexpr int BM = 128, BNT = 128, BK = 16;
    __shared__ float As[2][BK][BM];    // 16KB
    __shared__ float Bs[4][BK][BNT];   // 32KB  (total 48KB static, 2 CTAs/SM)

    const int tid = threadIdx.x;
    const int tx = tid & 15, ty = tid >> 4;
    const int by = blockIdx.y, bx = blockIdx.x;
    const int z = blockIdx.z;
    const int m0 = by * BM;
    const int n0 = bx * BNT;

    const float* A; float* C;
    if constexpr (LAYER == 1) { A = g_norm;               C = z ? g_h1d : g_h1c; }
    if constexpr (LAYER == 2) { A = z ? g_h1d : g_h1c;    C = z ? g_h2d : g_h2c; }
    if constexpr (LAYER == 3) { A = z ? g_h2d : g_h2c;    C = z ? g_h3d : g_h3c; }

    const float* W; const float* bias;
    if (z == 0) { W = Wc; bias = bc; }
    else {
        int dom = dom_of(m0);
        W = Wd + (size_t)dom * K * N;
        bias = bd + (size_t)dom * N;
    }

    // loader coords
    const int ar0 = tid >> 2, ar1 = ar0 + 64;
    const int ac0 = (tid & 3) * 4;
    const int bk0 = tid >> 5;                 // 0..7 (+8 for second chunk)
    const int bn0 = (tid & 31) * 4;
    const uint32_t sBu = smem_u32(Bs);

    u64 acc[8][4];
    #pragma unroll
    for (int i = 0; i < 8; i++)
        #pragma unroll
        for (int j = 0; j < 4; j++) acc[i][j] = 0ull;

    constexpr int NT = K / BK;
    static_assert(NT % 4 == 0, "NT must be divisible by 4");

    auto issueB = [&](int kt, int st) {       // k-tile kt -> ring stage st (st is literal)
        uint32_t dst = sBu + (uint32_t)(st * BK * BNT) * 4;
        const float* src = W + (size_t)kt * BK * N + n0 + bn0;
        cp_async16(dst + (bk0 * BNT + bn0) * 4,       src + (size_t)bk0 * N);
        cp_async16(dst + ((bk0 + 8) * BNT + bn0) * 4, src + (size_t)(bk0 + 8) * N);
        cp_commit();
    };
    auto ldgA = [&](int kt, float4* av) {
        const float* src = A + (size_t)m0 * K + kt * BK;
        av[0] = *(const float4*)&src[(size_t)ar0 * K + ac0];
        av[1] = *(const float4*)&src[(size_t)ar1 * K + ac0];
    };
    auto stsA = [&](int st, const float4* av) {
        As[st][ac0 + 0][ar0] = av[0].x;
        As[st][ac0 + 1][ar0] = av[0].y;
        As[st][ac0 + 2][ar0] = av[0].z;
        As[st][ac0 + 3][ar0] = av[0].w;
        As[st][ac0 + 0][ar1] = av[1].x;
        As[st][ac0 + 1][ar1] = av[1].y;
        As[st][ac0 + 2][ar1] = av[1].z;
        As[st][ac0 + 3][ar1] = av[1].w;
    };

    // prologue: A(0) -> As[0]; B(0) -> stage 0
    float4 av[2];
    ldgA(0, av);
    issueB(0, 0);
    stsA(0, av);

    for (int tq = 0; tq < NT; tq += 4) {
        #pragma unroll
        for (int u = 0; u < 4; u++) {
            const int t = tq + u;             // tile t lives in Bs stage u, As stage u&1
            const int sA = u & 1;
            if (t + 1 < NT) {
                ldgA(t + 1, av);              // private regs, race-free
                issueB(t + 1, (u + 1) & 3);   // literal stage, distance-2 safe
                cp_wait<1>();
            } else {
                cp_wait<0>();
            }
            __syncthreads();

            #pragma unroll
            for (int kk = 0; kk < BK; kk++) {
                float a[8];
                *(float4*)&a[0] = *(const float4*)&As[sA][kk][ty * 4];
                *(float4*)&a[4] = *(const float4*)&As[sA][kk][ty * 4 + 64];
                uint4 bq0 = *(const uint4*)&Bs[u][kk][tx * 4];
                uint4 bq1 = *(const uint4*)&Bs[u][kk][tx * 4 + 64];
                u64 b0 = ((const u64*)&bq0)[0], b1 = ((const u64*)&bq0)[1];
                u64 b2 = ((const u64*)&bq1)[0], b3 = ((const u64*)&bq1)[1];
                #pragma unroll
                for (int i = 0; i < 8; i++) {
                    u64 ai = pack2(a[i]);
                    fma2(acc[i][0], ai, b0);
                    fma2(acc[i][1], ai, b1);
                    fma2(acc[i][2], ai, b2);
                    fma2(acc[i][3], ai, b3);
                }
            }

            if (t + 1 < NT) stsA(sA ^ 1, av); // after compute: safe
        }
    }

    float bj[8];
    #pragma unroll
    for (int j = 0; j < 8; j++) {
        int cn = tx * 4 + (j & 3) + ((j >> 2) * 64);
        bj[j] = bias[n0 + cn];
    }
    #pragma unroll
    for (int i = 0; i < 8; i++) {
        int m = m0 + ty * 4 + (i & 3) + ((i >> 2) * 64);
        float2 c0 = unpack2(acc[i][0]);
        float2 c1 = unpack2(acc[i][1]);
        float2 c2 = unpack2(acc[i][2]);
        float2 c3 = unpack2(acc[i][3]);
        float4 o0, o1;
        o0.x = c0.x + bj[0]; o0.y = c0.y + bj[1];
        o0.z = c1.x + bj[2]; o0.w = c1.y + bj[3];
        o1.x = c2.x + bj[4]; o1.y = c2.y + bj[5];
        o1.z = c3.x + bj[6]; o1.w = c3.y + bj[7];
        if (RELU) {
            o0.x = fmaxf(o0.x, 0.f); o0.y = fmaxf(o0.y, 0.f);
            o0.z = fmaxf(o0.z, 0.f); o0.w = fmaxf(o0.w, 0.f);
            o1.x = fmaxf(o1.x, 0.f); o1.y = fmaxf(o1.y, 0.f);
            o1.z = fmaxf(o1.z, 0.f); o1.w = fmaxf(o1.w, 0.f);
        }
        *(float4*)&C[(size_t)m * N + n0 + tx * 4]      = o0;
        *(float4*)&C[(size_t)m * N + n0 + tx * 4 + 64] = o1;
    }
}

// ---------------- fuse + final MLP + aux + sigmoid ----------------
// 32 rows per block in 4 groups of 8 (reuses the 32KB fW1 smem image 4x).
__global__ __launch_bounds__(256) void final_kernel(const float* __restrict__ fW1,
                                                    const float* __restrict__ fb1,
                                                    const float* __restrict__ fW2,
                                                    const float* __restrict__ fb2,
                                                    float* __restrict__ out) {
    __shared__ float sW1[H3 * FH];
    __shared__ float sb1[FH], sW2[FH];
    __shared__ float sf[8][H3];

    int tid = threadIdx.x;
    for (int i = tid; i < H3 * FH; i += 256) sW1[i] = fW1[i];
    if (tid < FH) { sb1[tid] = fb1[tid]; sW2[tid] = fW2[tid]; }
    __syncthreads();

    int w = tid >> 5, lane = tid & 31;

    #pragma unroll
    for (int grp = 0; grp < 4; grp++) {
        int p = blockIdx.x * 32 + grp * 8 + w;
        int d0 = dom_of(p);
        bool pad = (p - g_off[d0]) >= g_cnt[d0];

        #pragma unroll
        for (int q = 0; q < 4; q++) {
            int i = q * 32 + lane;
            float c = g_h3c[(size_t)p * H3 + i];
            float d = g_h3d[(size_t)p * H3 + i];
            sf[w][i] = c * tanhf(d);
        }
        __syncwarp();

        float acc = 0.f;
        #pragma unroll
        for (int jj = 0; jj < 2; jj++) {
            int j = jj * 32 + lane;
            float h = sb1[j];
            #pragma unroll 8
            for (int i = 0; i < H3; i++) h += sf[w][i] * sW1[i * FH + j];
            acc += fmaxf(h, 0.f) * sW2[j];
        }
        #pragma unroll
        for (int o = 16; o; o >>= 1) acc += __shfl_xor_sync(0xFFFFFFFFu, acc, o);

        if (lane == 0 && !pad) {
            int r = g_perm[p];
            float v = acc + fb2[0] + g_aux[d0];
            out[r] = 1.f / (1.f + expf(-v));
        }
        __syncwarp();
    }
}

// ---------------- launch ----------------
extern "C" void kernel_launch(void* const* d_in, const int* in_sizes, int n_in,
                              void* d_out, int out_size) {
    const float* x      = (const float*)d_in[0];
    const int*   dids   = (const int*)  d_in[1];
    const float* pnw    = (const float*)d_in[2];
    const float* pnb    = (const float*)d_in[3];
    const float* cW1    = (const float*)d_in[4];
    const float* cb1    = (const float*)d_in[5];
    const float* cW2    = (const float*)d_in[6];
    const float* cb2    = (const float*)d_in[7];
    const float* cW3    = (const float*)d_in[8];
    const float* cb3    = (const float*)d_in[9];
    const float* dW1    = (const float*)d_in[10];
    const float* db1    = (const float*)d_in[11];
    const float* dW2    = (const float*)d_in[12];
    const float* db2    = (const float*)d_in[13];
    const float* dW3    = (const float*)d_in[14];
    const float* db3    = (const float*)d_in[15];
    const float* fW1    = (const float*)d_in[16];
    const float* fb1    = (const float*)d_in[17];
    const float* fW2    = (const float*)d_in[18];
    const float* fb2    = (const float*)d_in[19];
    const float* dom_emb= (const float*)d_in[20];
    const float* aW1    = (const float*)d_in[21];
    const float* ab1    = (const float*)d_in[22];
    const float* aW2    = (const float*)d_in[23];
    const float* ab2    = (const float*)d_in[24];
    float* out = (float*)d_out;

    count_kernel<<<NCB, 256>>>(dids);                 // 0
    scatter_kernel<<<NCB, 256>>>(dids);               // 1
    ln_kernel<<<BP, 256>>>(x, dids, pnw, pnb);        // 2

    gemm_kernel<D_IN, H1, true,  1>                   // 3
        <<<dim3(H1 / 128, BP / 128, 2), 256>>>(cW1, dW1, cb1, db1);
    gemm_kernel<H1,   H2, true,  2>                   // 4
        <<<dim3(H2 / 128, BP / 128, 2), 256>>>(cW2, dW2, cb2, db2);
    gemm_kernel<H2,   H3, false, 3>                   // 5
        <<<dim3(H3 / 128, BP / 128, 2), 256>>>(cW3, dW3, cb3, db3);

    aux_kernel<<<1, 128>>>(dom_emb, aW1, ab1, aW2, ab2);     // 6
    final_kernel<<<BP / 32, 256>>>(fW1, fb1, fW2, fb2, out); // 7
}